// round 7
// baseline (speedup 1.0000x reference)
#include <cuda_runtime.h>
#include <math.h>
#include <stdint.h>

// Problem constants
#define BB   2
#define NXQ  512
#define NCC  4096
#define DD   1024
#define HH   16
#define HDD  64
#define MROWS 1024            // B*NX
#define NEGF (-3.402823466e38f)

// Scratch (no cudaMalloc allowed)
__device__ float g_xn[MROWS * DD];
__device__ float g_q[MROWS * DD];
__device__ float g_attn[MROWS * DD];

// ---------------------------------------------------------------------------
// LayerNorm: one block per row (1024 rows of 1024), 256 threads, float4 loads
// ---------------------------------------------------------------------------
__global__ __launch_bounds__(256) void ln_kernel(const float* __restrict__ x,
                                                 const float* __restrict__ w,
                                                 const float* __restrict__ b) {
    int row = blockIdx.x;
    int t = threadIdx.x;
    const float4* xr = (const float4*)(x + (size_t)row * DD);
    float4 v = xr[t];
    float s = v.x + v.y + v.z + v.w;
    __shared__ float red[8];
#pragma unroll
    for (int o = 16; o; o >>= 1) s += __shfl_xor_sync(0xffffffffu, s, o);
    if ((t & 31) == 0) red[t >> 5] = s;
    __syncthreads();
    float tot = 0.f;
#pragma unroll
    for (int i = 0; i < 8; i++) tot += red[i];
    float mu = tot * (1.0f / 1024.0f);
    float dx = v.x - mu, dy = v.y - mu, dz = v.z - mu, dw = v.w - mu;
    float s2 = dx * dx + dy * dy + dz * dz + dw * dw;
#pragma unroll
    for (int o = 16; o; o >>= 1) s2 += __shfl_xor_sync(0xffffffffu, s2, o);
    __syncthreads();   // all reads of red done before reuse
    if ((t & 31) == 0) red[t >> 5] = s2;
    __syncthreads();
    float tot2 = 0.f;
#pragma unroll
    for (int i = 0; i < 8; i++) tot2 += red[i];
    float inv = rsqrtf(tot2 * (1.0f / 1024.0f) + 1e-5f);
    float4 wv = ((const float4*)w)[t];
    float4 bv = ((const float4*)b)[t];
    float4 o4;
    o4.x = dx * inv * wv.x + bv.x;
    o4.y = dy * inv * wv.y + bv.y;
    o4.z = dz * inv * wv.z + bv.z;
    o4.w = dw * inv * wv.w + bv.w;
    ((float4*)(g_xn + (size_t)row * DD))[t] = o4;
}

// ---------------------------------------------------------------------------
// SGEMM: C(1024x1024) = A(1024x1024) @ B(1024x1024), fp32
// 64x64 block tile, BK=16, 256 threads, 4x4 micro-tile
// ---------------------------------------------------------------------------
__global__ __launch_bounds__(256) void sgemm_kernel(const float* __restrict__ A,
                                                    const float* __restrict__ Bm,
                                                    float* __restrict__ C) {
    __shared__ float As[16][64];
    __shared__ float Bs[16][64];
    int t = threadIdx.x;
    int tx = t & 15, ty = t >> 4;
    int arow = blockIdx.y * 64, bcol = blockIdx.x * 64;
    float acc[4][4] = {};
    int am = t >> 2, ak = (t & 3) * 4;
    int bk = t >> 4, bn = (t & 15) * 4;
    for (int k0 = 0; k0 < 1024; k0 += 16) {
        float4 av = *(const float4*)(A + (size_t)(arow + am) * 1024 + k0 + ak);
        As[ak + 0][am] = av.x;
        As[ak + 1][am] = av.y;
        As[ak + 2][am] = av.z;
        As[ak + 3][am] = av.w;
        float4 bv = *(const float4*)(Bm + (size_t)(k0 + bk) * 1024 + bcol + bn);
        *(float4*)&Bs[bk][bn] = bv;
        __syncthreads();
#pragma unroll
        for (int kk = 0; kk < 16; kk++) {
            float4 a4 = *(const float4*)&As[kk][ty * 4];
            float4 b4 = *(const float4*)&Bs[kk][tx * 4];
            float a[4] = {a4.x, a4.y, a4.z, a4.w};
            float bb[4] = {b4.x, b4.y, b4.z, b4.w};
#pragma unroll
            for (int i = 0; i < 4; i++)
#pragma unroll
                for (int j = 0; j < 4; j++) acc[i][j] += a[i] * bb[j];
        }
        __syncthreads();
    }
#pragma unroll
    for (int i = 0; i < 4; i++) {
        float4 o4 = {acc[i][0], acc[i][1], acc[i][2], acc[i][3]};
        *(float4*)(C + (size_t)(arow + ty * 4 + i) * 1024 + bcol + tx * 4) = o4;
    }
}

// ---------------------------------------------------------------------------
// Flash attention, fp32. Block = (b, h, 64-query tile). 256 threads (16x16).
// Keys = [Q block (512, all unmasked), c block (4096, user mask)], V == K.
// smem pitch 68 (multiple of 4 -> aligned float4, stride 68%32=4 -> low conflicts)
// Mask is int32 (harness coerces numpy bool -> int32).
// ---------------------------------------------------------------------------
#define PITCH 68
#define ATT_SMEM_BYTES (3 * 64 * PITCH * 4 + 64 * 64)

__global__ __launch_bounds__(256) void attn_kernel(const int* __restrict__ gmask,
                                                   const float* __restrict__ gc) {
    extern __shared__ float smem[];
    float* Qs = smem;                         // [64][PITCH]
    float* Ks = smem + 64 * PITCH;            // [64][PITCH]
    float* Ps = smem + 2 * 64 * PITCH;        // [64][PITCH]
    unsigned char* Ms = (unsigned char*)(smem + 3 * 64 * PITCH);  // [64*64]

    const int b = blockIdx.z, h = blockIdx.y, q0 = blockIdx.x * 64;
    const int t = threadIdx.x;
    const int tx = t & 15, ty = t >> 4;
    const int lrow = t >> 2;
    const int lcol = (t & 3) * 16;

    // Load Q tile once
    {
        const float* src = g_q + (size_t)(b * NXQ + q0 + lrow) * DD + h * HDD + lcol;
#pragma unroll
        for (int i = 0; i < 4; i++) {
            float4 v = *(const float4*)(src + i * 4);
            float* d = &Qs[lrow * PITCH + lcol + i * 4];
            d[0] = v.x; d[1] = v.y; d[2] = v.z; d[3] = v.w;
        }
    }

    float acc[4][4] = {};
    float m_i[4], l_i[4];
#pragma unroll
    for (int i = 0; i < 4; i++) { m_i[i] = NEGF; l_i[i] = 0.f; }

    const float scale = 0.125f;  // 64^-0.5

    for (int kt = 0; kt < 72; kt++) {
        const bool isq = (kt < 8);
        // Load K tile (and mask tile for context part). Previous GEMM2 use of
        // Ks is fenced by the loop-tail __syncthreads().
        {
            const float* src = isq
                ? g_q + (size_t)(b * NXQ + kt * 64 + lrow) * DD + h * HDD + lcol
                : gc  + (size_t)(b * NCC + (kt - 8) * 64 + lrow) * DD + h * HDD + lcol;
#pragma unroll
            for (int i = 0; i < 4; i++) {
                float4 v = *(const float4*)(src + i * 4);
                float* d = &Ks[lrow * PITCH + lcol + i * 4];
                d[0] = v.x; d[1] = v.y; d[2] = v.z; d[3] = v.w;
            }
            if (!isq) {
                // mask is int32: load 16 ints (4x int4), pack to bytes
                const int* msrc = gmask + (size_t)(b * NXQ + q0 + lrow) * NCC +
                                  (kt - 8) * 64 + lcol;
                unsigned char* mdst = Ms + lrow * 64 + lcol;
#pragma unroll
                for (int i = 0; i < 4; i++) {
                    int4 mv = *(const int4*)(msrc + i * 4);
                    mdst[i * 4 + 0] = (unsigned char)(mv.x != 0);
                    mdst[i * 4 + 1] = (unsigned char)(mv.y != 0);
                    mdst[i * 4 + 2] = (unsigned char)(mv.z != 0);
                    mdst[i * 4 + 3] = (unsigned char)(mv.w != 0);
                }
            }
        }
        __syncthreads();

        // S = Q @ K^T (64x64x64)
        float s[4][4] = {};
#pragma unroll
        for (int d0 = 0; d0 < 64; d0 += 4) {
            float aq[4][4], kk4[4][4];
#pragma unroll
            for (int i = 0; i < 4; i++) {
                float4 v = *(const float4*)&Qs[(ty * 4 + i) * PITCH + d0];
                aq[i][0] = v.x; aq[i][1] = v.y; aq[i][2] = v.z; aq[i][3] = v.w;
            }
#pragma unroll
            for (int j = 0; j < 4; j++) {
                float4 v = *(const float4*)&Ks[(tx * 4 + j) * PITCH + d0];
                kk4[j][0] = v.x; kk4[j][1] = v.y; kk4[j][2] = v.z; kk4[j][3] = v.w;
            }
#pragma unroll
            for (int i = 0; i < 4; i++)
#pragma unroll
                for (int j = 0; j < 4; j++) {
                    s[i][j] += aq[i][0] * kk4[j][0];
                    s[i][j] += aq[i][1] * kk4[j][1];
                    s[i][j] += aq[i][2] * kk4[j][2];
                    s[i][j] += aq[i][3] * kk4[j][3];
                }
        }

        // scale + mask
#pragma unroll
        for (int i = 0; i < 4; i++)
#pragma unroll
            for (int j = 0; j < 4; j++) {
                float sv = s[i][j] * scale;
                if (!isq) {
                    if (!Ms[(ty * 4 + i) * 64 + tx * 4 + j]) sv = NEGF;
                }
                s[i][j] = sv;
            }

        // Online softmax update (row groups of 16 lanes along tx)
#pragma unroll
        for (int i = 0; i < 4; i++) {
            float mx = fmaxf(fmaxf(s[i][0], s[i][1]), fmaxf(s[i][2], s[i][3]));
#pragma unroll
            for (int o = 8; o; o >>= 1) mx = fmaxf(mx, __shfl_xor_sync(0xffffffffu, mx, o));
            float mnew = fmaxf(m_i[i], mx);
            float alpha = __expf(m_i[i] - mnew);
            m_i[i] = mnew;
            float ps = 0.f;
#pragma unroll
            for (int j = 0; j < 4; j++) {
                float p = __expf(s[i][j] - mnew);
                s[i][j] = p;
                ps += p;
            }
#pragma unroll
            for (int o = 8; o; o >>= 1) ps += __shfl_xor_sync(0xffffffffu, ps, o);
            l_i[i] = l_i[i] * alpha + ps;
#pragma unroll
            for (int j = 0; j < 4; j++) acc[i][j] *= alpha;
        }

        // Store P tile (previous reads of Ps fenced by loop-tail sync)
#pragma unroll
        for (int i = 0; i < 4; i++) {
            float4 o4 = {s[i][0], s[i][1], s[i][2], s[i][3]};
            *(float4*)&Ps[(ty * 4 + i) * PITCH + tx * 4] = o4;
        }
        __syncthreads();

        // acc += P @ V (V == K tile), 64x64x64
#pragma unroll
        for (int k0 = 0; k0 < 64; k0 += 4) {
            float p_arr[4][4];
#pragma unroll
            for (int i = 0; i < 4; i++) {
                float4 v = *(const float4*)&Ps[(ty * 4 + i) * PITCH + k0];
                p_arr[i][0] = v.x; p_arr[i][1] = v.y; p_arr[i][2] = v.z; p_arr[i][3] = v.w;
            }
#pragma unroll
            for (int kk = 0; kk < 4; kk++) {
                float4 vv = *(const float4*)&Ks[(k0 + kk) * PITCH + tx * 4];
#pragma unroll
                for (int i = 0; i < 4; i++) {
                    acc[i][0] += p_arr[i][kk] * vv.x;
                    acc[i][1] += p_arr[i][kk] * vv.y;
                    acc[i][2] += p_arr[i][kk] * vv.z;
                    acc[i][3] += p_arr[i][kk] * vv.w;
                }
            }
        }
        __syncthreads();
    }

    // Epilogue: normalize and write to g_attn in (row=b*NX+q, col=h*HD+d) layout
#pragma unroll
    for (int i = 0; i < 4; i++) {
        float inv = 1.0f / l_i[i];
        float4 o4 = {acc[i][0] * inv, acc[i][1] * inv, acc[i][2] * inv, acc[i][3] * inv};
        *(float4*)(g_attn + (size_t)(b * NXQ + q0 + ty * 4 + i) * DD + h * HDD + tx * 4) = o4;
    }
}

// ---------------------------------------------------------------------------
// kv0: out2[((b*16+h)*4096 + k)*64 + d] = c[(b*4096+k)*1024 + h*64 + d]
// ---------------------------------------------------------------------------
__global__ __launch_bounds__(256) void kv0_kernel(const float* __restrict__ c,
                                                  float* __restrict__ out2) {
    int idx = blockIdx.x * 256 + threadIdx.x;  // float4 index, 2,097,152 total
    if (idx >= 2097152) return;
    int d4 = idx & 15;
    int k = (idx >> 4) & 4095;
    int h = (idx >> 16) & 15;
    int b = idx >> 20;
    float4 v = *(const float4*)(c + (size_t)(b * NCC + k) * DD + h * HDD + d4 * 4);
    *(float4*)(out2 + (size_t)idx * 4) = v;
}

// ---------------------------------------------------------------------------
extern "C" void kernel_launch(void* const* d_in, const int* in_sizes, int n_in,
                              void* d_out, int out_size) {
    const float* x = (const float*)d_in[0];
    const float* c = (const float*)d_in[1];
    const int* mask = (const int*)d_in[2];   // bool coerced to int32 by harness
    const float* lnw = (const float*)d_in[3];
    const float* lnb = (const float*)d_in[4];
    const float* Wq = (const float*)d_in[5];
    const float* Wo = (const float*)d_in[6];
    float* out = (float*)d_out;

    float *p_xn, *p_q, *p_attn;
    cudaGetSymbolAddress((void**)&p_xn, g_xn);
    cudaGetSymbolAddress((void**)&p_q, g_q);
    cudaGetSymbolAddress((void**)&p_attn, g_attn);

    // 1) LayerNorm
    ln_kernel<<<MROWS, 256>>>(x, lnw, lnb);

    // 2) Q = xn @ Wq
    sgemm_kernel<<<dim3(16, 16), 256>>>(p_xn, Wq, p_q);

    // 3) Flash attention over [Q-keys | c-keys]
    cudaFuncSetAttribute(attn_kernel, cudaFuncAttributeMaxDynamicSharedMemorySize,
                         ATT_SMEM_BYTES);
    attn_kernel<<<dim3(NXQ / 64, HH, BB), 256, ATT_SMEM_BYTES>>>(mask, c);

    // 4) o = a @ Wo  (written straight into output)
    sgemm_kernel<<<dim3(16, 16), 256>>>(p_attn, Wo, out);

    // 5) kv0 transpose into second output region
    if (out_size >= 9437184) {
        kv0_kernel<<<2097152 / 256, 256>>>(c, out + 1048576);
    }
}

// round 8
// speedup vs baseline: 2.4748x; 2.4748x over previous
#include <cuda_runtime.h>
#include <math.h>
#include <stdint.h>

// Problem constants
#define BB   2
#define NXQ  512
#define NCC  4096
#define DD   1024
#define HH   16
#define HDD  64
#define MROWS 1024            // B*NX
#define NEGF (-3.402823466e38f)

// Scratch (no cudaMalloc allowed)
__device__ float g_xn[MROWS * DD];
__device__ float g_q[MROWS * DD];
__device__ float g_attn[MROWS * DD];
__device__ unsigned int g_mbits[MROWS * (NCC / 32)];  // packed mask bits, 512KB

// ---------------------------------------------------------------------------
// helpers: tf32 conversion + m16n8k8 tf32 mma
// ---------------------------------------------------------------------------
__device__ __forceinline__ unsigned int f2tf32(float x) {
    unsigned int r;
    asm("cvt.rna.tf32.f32 %0, %1;" : "=r"(r) : "f"(x));
    return r;
}

__device__ __forceinline__ void mma_tf32(float* d, const unsigned int* a,
                                         const unsigned int* b) {
    asm volatile(
        "mma.sync.aligned.m16n8k8.row.col.f32.tf32.tf32.f32 "
        "{%0,%1,%2,%3}, {%4,%5,%6,%7}, {%8,%9}, {%0,%1,%2,%3};"
        : "+f"(d[0]), "+f"(d[1]), "+f"(d[2]), "+f"(d[3])
        : "r"(a[0]), "r"(a[1]), "r"(a[2]), "r"(a[3]), "r"(b[0]), "r"(b[1]));
}

// ---------------------------------------------------------------------------
// LayerNorm: one block per row (1024 rows of 1024), 256 threads, float4 loads
// ---------------------------------------------------------------------------
__global__ __launch_bounds__(256) void ln_kernel(const float* __restrict__ x,
                                                 const float* __restrict__ w,
                                                 const float* __restrict__ b) {
    int row = blockIdx.x;
    int t = threadIdx.x;
    const float4* xr = (const float4*)(x + (size_t)row * DD);
    float4 v = xr[t];
    float s = v.x + v.y + v.z + v.w;
    __shared__ float red[8];
#pragma unroll
    for (int o = 16; o; o >>= 1) s += __shfl_xor_sync(0xffffffffu, s, o);
    if ((t & 31) == 0) red[t >> 5] = s;
    __syncthreads();
    float tot = 0.f;
#pragma unroll
    for (int i = 0; i < 8; i++) tot += red[i];
    float mu = tot * (1.0f / 1024.0f);
    float dx = v.x - mu, dy = v.y - mu, dz = v.z - mu, dw = v.w - mu;
    float s2 = dx * dx + dy * dy + dz * dz + dw * dw;
#pragma unroll
    for (int o = 16; o; o >>= 1) s2 += __shfl_xor_sync(0xffffffffu, s2, o);
    __syncthreads();
    if ((t & 31) == 0) red[t >> 5] = s2;
    __syncthreads();
    float tot2 = 0.f;
#pragma unroll
    for (int i = 0; i < 8; i++) tot2 += red[i];
    float inv = rsqrtf(tot2 * (1.0f / 1024.0f) + 1e-5f);
    float4 wv = ((const float4*)w)[t];
    float4 bv = ((const float4*)b)[t];
    float4 o4;
    o4.x = dx * inv * wv.x + bv.x;
    o4.y = dy * inv * wv.y + bv.y;
    o4.z = dz * inv * wv.z + bv.z;
    o4.w = dw * inv * wv.w + bv.w;
    ((float4*)(g_xn + (size_t)row * DD))[t] = o4;
}

// ---------------------------------------------------------------------------
// SGEMM: C(1024x1024) = A @ B, fp32, 64x64 tile (unchanged this round)
// ---------------------------------------------------------------------------
__global__ __launch_bounds__(256) void sgemm_kernel(const float* __restrict__ A,
                                                    const float* __restrict__ Bm,
                                                    float* __restrict__ C) {
    __shared__ float As[16][64];
    __shared__ float Bs[16][64];
    int t = threadIdx.x;
    int tx = t & 15, ty = t >> 4;
    int arow = blockIdx.y * 64, bcol = blockIdx.x * 64;
    float acc[4][4] = {};
    int am = t >> 2, ak = (t & 3) * 4;
    int bk = t >> 4, bn = (t & 15) * 4;
    for (int k0 = 0; k0 < 1024; k0 += 16) {
        float4 av = *(const float4*)(A + (size_t)(arow + am) * 1024 + k0 + ak);
        As[ak + 0][am] = av.x;
        As[ak + 1][am] = av.y;
        As[ak + 2][am] = av.z;
        As[ak + 3][am] = av.w;
        float4 bv = *(const float4*)(Bm + (size_t)(k0 + bk) * 1024 + bcol + bn);
        *(float4*)&Bs[bk][bn] = bv;
        __syncthreads();
#pragma unroll
        for (int kk = 0; kk < 16; kk++) {
            float4 a4 = *(const float4*)&As[kk][ty * 4];
            float4 b4 = *(const float4*)&Bs[kk][tx * 4];
            float a[4] = {a4.x, a4.y, a4.z, a4.w};
            float bb[4] = {b4.x, b4.y, b4.z, b4.w};
#pragma unroll
            for (int i = 0; i < 4; i++)
#pragma unroll
                for (int j = 0; j < 4; j++) acc[i][j] += a[i] * bb[j];
        }
        __syncthreads();
    }
#pragma unroll
    for (int i = 0; i < 4; i++) {
        float4 o4 = {acc[i][0], acc[i][1], acc[i][2], acc[i][3]};
        *(float4*)(C + (size_t)(arow + ty * 4 + i) * 1024 + bcol + tx * 4) = o4;
    }
}

// ---------------------------------------------------------------------------
// Mask packer: int32 mask (B,NX,NC) -> bitmask, 1 warp per row, ballot.
// ---------------------------------------------------------------------------
__global__ __launch_bounds__(256) void maskpack_kernel(const int* __restrict__ mask) {
    int row = blockIdx.x * 8 + (threadIdx.x >> 5);  // 0..1023
    int lane = threadIdx.x & 31;
    const int* src = mask + (size_t)row * NCC;
    unsigned int* dst = g_mbits + (size_t)row * (NCC / 32);
    for (int i = 0; i < NCC / 32; i++) {
        unsigned int v = __ballot_sync(0xffffffffu, src[i * 32 + lane] != 0);
        if (lane == 0) dst[i] = v;
    }
}

// ---------------------------------------------------------------------------
// Flash attention with tf32 mma.sync (m16n8k8).
// Block = (64-query tile, h, b), 128 threads (4 warps), warp owns 16 rows.
// Keys = [Q block (8 tiles, unmasked), c block (64 tiles, bitmask)], V == K.
// ---------------------------------------------------------------------------
#define KP 68   // K-tile smem pitch (floats): conflict-free for S B-frag / P A-frag
#define PP 68   // P smem pitch

__global__ __launch_bounds__(128) void attn_mma_kernel(const float* __restrict__ gc) {
    __shared__ float Ks[64 * KP];        // K tile (tf32 bit pattern stored as float)
    __shared__ float Ps[4][16 * PP];     // per-warp P tile

    const int b = blockIdx.z, h = blockIdx.y, q0 = blockIdx.x * 64;
    const int t = threadIdx.x;
    const int w = t >> 5, lane = t & 31;
    const int g = lane >> 2, c = lane & 3;
    const int rowA = q0 + w * 16 + g;    // global q row within batch (rowB = rowA+8)

    // ---- Q A-fragments (held in registers for all 72 k-tiles), scale folded in
    unsigned int qa[8][4];
    {
        const float* qb = g_q + ((size_t)(b * NXQ + rowA)) * DD + h * HDD;
#pragma unroll
        for (int ks = 0; ks < 8; ks++) {
            qa[ks][0] = f2tf32(qb[ks * 8 + c] * 0.125f);
            qa[ks][1] = f2tf32(qb[8 * DD + ks * 8 + c] * 0.125f);
            qa[ks][2] = f2tf32(qb[ks * 8 + c + 4] * 0.125f);
            qa[ks][3] = f2tf32(qb[8 * DD + ks * 8 + c + 4] * 0.125f);
        }
    }

    float o[8][4] = {};
    float m0 = NEGF, m1 = NEGF, l0 = 0.f, l1 = 0.f;

    // K tile loader mapping: 128 threads x 32 floats = 64x64
    const int lrow = t >> 1, lc0 = (t & 1) * 32;

    for (int kt = 0; kt < 72; kt++) {
        const bool isq = (kt < 8);

        // Prefetch K tile into registers (before the sync that frees Ks)
        float4 kv[8];
        {
            const float* src = isq
                ? g_q + ((size_t)(b * NXQ + kt * 64 + lrow)) * DD + h * HDD + lc0
                : gc  + ((size_t)(b * NCC + (kt - 8) * 64 + lrow)) * DD + h * HDD + lc0;
#pragma unroll
            for (int i = 0; i < 8; i++) kv[i] = *(const float4*)(src + i * 4);
        }
        // Mask words for this tile (2 words x 2 rows)
        unsigned int mw0a = ~0u, mw1a = ~0u, mw0b = ~0u, mw1b = ~0u;
        if (!isq) {
            const unsigned int* mr =
                g_mbits + (size_t)(b * NXQ + rowA) * (NCC / 32) + (kt - 8) * 2;
            mw0a = mr[0];
            mw1a = mr[1];
            mw0b = mr[8 * (NCC / 32)];
            mw1b = mr[8 * (NCC / 32) + 1];
        }

        __syncthreads();  // previous PV phase done reading Ks
#pragma unroll
        for (int i = 0; i < 8; i++) {
            float4 cv;
            cv.x = __uint_as_float(f2tf32(kv[i].x));
            cv.y = __uint_as_float(f2tf32(kv[i].y));
            cv.z = __uint_as_float(f2tf32(kv[i].z));
            cv.w = __uint_as_float(f2tf32(kv[i].w));
            *(float4*)&Ks[lrow * KP + lc0 + i * 4] = cv;
        }
        __syncthreads();  // tile ready

        // ---- S = (Q*scale) @ K^T : 8 n-blocks x 8 k-steps of m16n8k8
        float s[8][4] = {};
#pragma unroll
        for (int ks = 0; ks < 8; ks++) {
#pragma unroll
            for (int nb = 0; nb < 8; nb++) {
                unsigned int bk[2];
                bk[0] = __float_as_uint(Ks[(nb * 8 + g) * KP + ks * 8 + c]);
                bk[1] = __float_as_uint(Ks[(nb * 8 + g) * KP + ks * 8 + c + 4]);
                mma_tf32(s[nb], qa[ks], bk);
            }
        }

        // ---- mask
        if (!isq) {
#pragma unroll
            for (int nb = 0; nb < 8; nb++) {
                unsigned int wa = (nb < 4) ? mw0a : mw1a;
                unsigned int wb = (nb < 4) ? mw0b : mw1b;
                int bit0 = (nb & 3) * 8 + 2 * c;
                if (!((wa >> bit0) & 1u)) s[nb][0] = NEGF;
                if (!((wa >> (bit0 + 1)) & 1u)) s[nb][1] = NEGF;
                if (!((wb >> bit0) & 1u)) s[nb][2] = NEGF;
                if (!((wb >> (bit0 + 1)) & 1u)) s[nb][3] = NEGF;
            }
        }

        // ---- online softmax (rows rowA: regs 0,1 ; rowA+8: regs 2,3)
        float mx0 = NEGF, mx1 = NEGF;
#pragma unroll
        for (int nb = 0; nb < 8; nb++) {
            mx0 = fmaxf(mx0, fmaxf(s[nb][0], s[nb][1]));
            mx1 = fmaxf(mx1, fmaxf(s[nb][2], s[nb][3]));
        }
        mx0 = fmaxf(mx0, __shfl_xor_sync(0xffffffffu, mx0, 1));
        mx0 = fmaxf(mx0, __shfl_xor_sync(0xffffffffu, mx0, 2));
        mx1 = fmaxf(mx1, __shfl_xor_sync(0xffffffffu, mx1, 1));
        mx1 = fmaxf(mx1, __shfl_xor_sync(0xffffffffu, mx1, 2));
        float mn0 = fmaxf(m0, mx0), mn1 = fmaxf(m1, mx1);
        float a0 = __expf(m0 - mn0), a1 = __expf(m1 - mn1);
        m0 = mn0;
        m1 = mn1;
        float ps0 = 0.f, ps1 = 0.f;
#pragma unroll
        for (int nb = 0; nb < 8; nb++) {
            s[nb][0] = __expf(s[nb][0] - mn0);
            s[nb][1] = __expf(s[nb][1] - mn0);
            s[nb][2] = __expf(s[nb][2] - mn1);
            s[nb][3] = __expf(s[nb][3] - mn1);
            ps0 += s[nb][0] + s[nb][1];
            ps1 += s[nb][2] + s[nb][3];
        }
        ps0 += __shfl_xor_sync(0xffffffffu, ps0, 1);
        ps0 += __shfl_xor_sync(0xffffffffu, ps0, 2);
        ps1 += __shfl_xor_sync(0xffffffffu, ps1, 1);
        ps1 += __shfl_xor_sync(0xffffffffu, ps1, 2);
        l0 = l0 * a0 + ps0;
        l1 = l1 * a1 + ps1;
#pragma unroll
        for (int nb = 0; nb < 8; nb++) {
            o[nb][0] *= a0;
            o[nb][1] *= a0;
            o[nb][2] *= a1;
            o[nb][3] *= a1;
        }

        // ---- store P (tf32 bits) to per-warp smem, C-frag layout
        float* pw = Ps[w];
#pragma unroll
        for (int nb = 0; nb < 8; nb++) {
            float2 v0, v1;
            v0.x = __uint_as_float(f2tf32(s[nb][0]));
            v0.y = __uint_as_float(f2tf32(s[nb][1]));
            v1.x = __uint_as_float(f2tf32(s[nb][2]));
            v1.y = __uint_as_float(f2tf32(s[nb][3]));
            *(float2*)&pw[g * PP + nb * 8 + 2 * c] = v0;
            *(float2*)&pw[(g + 8) * PP + nb * 8 + 2 * c] = v1;
        }
        __syncwarp();

        // ---- O += P @ V  (V == K tile): K-dim = 64 keys (8 steps), N = 64 d
#pragma unroll
        for (int ks = 0; ks < 8; ks++) {
            unsigned int pa[4];
            pa[0] = __float_as_uint(pw[g * PP + ks * 8 + c]);
            pa[1] = __float_as_uint(pw[(g + 8) * PP + ks * 8 + c]);
            pa[2] = __float_as_uint(pw[g * PP + ks * 8 + c + 4]);
            pa[3] = __float_as_uint(pw[(g + 8) * PP + ks * 8 + c + 4]);
#pragma unroll
            for (int nb = 0; nb < 8; nb++) {
                unsigned int bv[2];
                bv[0] = __float_as_uint(Ks[(ks * 8 + c) * KP + nb * 8 + g]);
                bv[1] = __float_as_uint(Ks[(ks * 8 + c + 4) * KP + nb * 8 + g]);
                mma_tf32(o[nb], pa, bv);
            }
        }
        __syncwarp();  // P reads done before next iteration overwrites Ps[w]
    }

    // ---- epilogue: normalize, write g_attn (row=b*NX+q, col=h*HD+d)
    float inv0 = 1.0f / l0, inv1 = 1.0f / l1;
    float* ob = g_attn + ((size_t)(b * NXQ + rowA)) * DD + h * HDD;
#pragma unroll
    for (int nb = 0; nb < 8; nb++) {
        float2 v0 = {o[nb][0] * inv0, o[nb][1] * inv0};
        float2 v1 = {o[nb][2] * inv1, o[nb][3] * inv1};
        *(float2*)(ob + nb * 8 + 2 * c) = v0;
        *(float2*)(ob + 8 * DD + nb * 8 + 2 * c) = v1;
    }
}

// ---------------------------------------------------------------------------
// kv0: out2[((b*16+h)*4096 + k)*64 + d] = c[(b*4096+k)*1024 + h*64 + d]
// ---------------------------------------------------------------------------
__global__ __launch_bounds__(256) void kv0_kernel(const float* __restrict__ c,
                                                  float* __restrict__ out2) {
    int idx = blockIdx.x * 256 + threadIdx.x;  // float4 index
    if (idx >= 2097152) return;
    int d4 = idx & 15;
    int k = (idx >> 4) & 4095;
    int h = (idx >> 16) & 15;
    int b = idx >> 20;
    float4 v = *(const float4*)(c + (size_t)(b * NCC + k) * DD + h * HDD + d4 * 4);
    *(float4*)(out2 + (size_t)idx * 4) = v;
}

// ---------------------------------------------------------------------------
extern "C" void kernel_launch(void* const* d_in, const int* in_sizes, int n_in,
                              void* d_out, int out_size) {
    const float* x = (const float*)d_in[0];
    const float* c = (const float*)d_in[1];
    const int* mask = (const int*)d_in[2];   // bool coerced to int32 by harness
    const float* lnw = (const float*)d_in[3];
    const float* lnb = (const float*)d_in[4];
    const float* Wq = (const float*)d_in[5];
    const float* Wo = (const float*)d_in[6];
    float* out = (float*)d_out;

    float *p_xn, *p_q, *p_attn;
    cudaGetSymbolAddress((void**)&p_xn, g_xn);
    cudaGetSymbolAddress((void**)&p_q, g_q);
    cudaGetSymbolAddress((void**)&p_attn, g_attn);

    // 0) pack mask to bits (independent of LN/GEMM)
    maskpack_kernel<<<MROWS / 8, 256>>>(mask);

    // 1) LayerNorm
    ln_kernel<<<MROWS, 256>>>(x, lnw, lnb);

    // 2) Q = xn @ Wq
    sgemm_kernel<<<dim3(16, 16), 256>>>(p_xn, Wq, p_q);

    // 3) Flash attention (tf32 tensor cores)
    attn_mma_kernel<<<dim3(NXQ / 64, HH, BB), 128>>>(c);

    // 4) o = a @ Wo (written straight into output)
    sgemm_kernel<<<dim3(16, 16), 256>>>(p_attn, Wo, out);

    // 5) kv0 transpose into second output region
    if (out_size >= 9437184) {
        kv0_kernel<<<2097152 / 256, 256>>>(c, out + 1048576);
    }
}

// round 9
// speedup vs baseline: 2.8525x; 1.1526x over previous
#include <cuda_runtime.h>
#include <math.h>
#include <stdint.h>

// Problem constants
#define BB   2
#define NXQ  512
#define NCC  4096
#define DD   1024
#define HH   16
#define HDD  64
#define MROWS 1024            // B*NX
#define NEGF (-3.402823466e38f)

// Scratch (no cudaMalloc allowed)
__device__ float g_xn[MROWS * DD];
__device__ float g_q[MROWS * DD];
__device__ float g_attn[MROWS * DD];
__device__ unsigned int g_mbits[MROWS * (NCC / 32)];  // packed mask bits

// ---------------------------------------------------------------------------
// helpers: tf32 conversion + m16n8k8 tf32 mma
// ---------------------------------------------------------------------------
__device__ __forceinline__ unsigned int f2tf32(float x) {
    unsigned int r;
    asm("cvt.rna.tf32.f32 %0, %1;" : "=r"(r) : "f"(x));
    return r;
}

__device__ __forceinline__ void mma_tf32(float* d, const unsigned int* a,
                                         const unsigned int* b) {
    asm volatile(
        "mma.sync.aligned.m16n8k8.row.col.f32.tf32.tf32.f32 "
        "{%0,%1,%2,%3}, {%4,%5,%6,%7}, {%8,%9}, {%0,%1,%2,%3};"
        : "+f"(d[0]), "+f"(d[1]), "+f"(d[2]), "+f"(d[3])
        : "r"(a[0]), "r"(a[1]), "r"(a[2]), "r"(a[3]), "r"(b[0]), "r"(b[1]));
}

// ---------------------------------------------------------------------------
// LayerNorm (unchanged, proven)
// ---------------------------------------------------------------------------
__global__ __launch_bounds__(256) void ln_kernel(const float* __restrict__ x,
                                                 const float* __restrict__ w,
                                                 const float* __restrict__ b) {
    int row = blockIdx.x;
    int t = threadIdx.x;
    const float4* xr = (const float4*)(x + (size_t)row * DD);
    float4 v = xr[t];
    float s = v.x + v.y + v.z + v.w;
    __shared__ float red[8];
#pragma unroll
    for (int o = 16; o; o >>= 1) s += __shfl_xor_sync(0xffffffffu, s, o);
    if ((t & 31) == 0) red[t >> 5] = s;
    __syncthreads();
    float tot = 0.f;
#pragma unroll
    for (int i = 0; i < 8; i++) tot += red[i];
    float mu = tot * (1.0f / 1024.0f);
    float dx = v.x - mu, dy = v.y - mu, dz = v.z - mu, dw = v.w - mu;
    float s2 = dx * dx + dy * dy + dz * dz + dw * dw;
#pragma unroll
    for (int o = 16; o; o >>= 1) s2 += __shfl_xor_sync(0xffffffffu, s2, o);
    __syncthreads();
    if ((t & 31) == 0) red[t >> 5] = s2;
    __syncthreads();
    float tot2 = 0.f;
#pragma unroll
    for (int i = 0; i < 8; i++) tot2 += red[i];
    float inv = rsqrtf(tot2 * (1.0f / 1024.0f) + 1e-5f);
    float4 wv = ((const float4*)w)[t];
    float4 bv = ((const float4*)b)[t];
    float4 o4;
    o4.x = dx * inv * wv.x + bv.x;
    o4.y = dy * inv * wv.y + bv.y;
    o4.z = dz * inv * wv.z + bv.z;
    o4.w = dw * inv * wv.w + bv.w;
    ((float4*)(g_xn + (size_t)row * DD))[t] = o4;
}

// ---------------------------------------------------------------------------
// Mask packer (unchanged, proven)
// ---------------------------------------------------------------------------
__global__ __launch_bounds__(256) void maskpack_kernel(const int* __restrict__ mask) {
    int row = blockIdx.x * 8 + (threadIdx.x >> 5);
    int lane = threadIdx.x & 31;
    const int* src = mask + (size_t)row * NCC;
    unsigned int* dst = g_mbits + (size_t)row * (NCC / 32);
    for (int i = 0; i < NCC / 32; i++) {
        unsigned int v = __ballot_sync(0xffffffffu, src[i * 32 + lane] != 0);
        if (lane == 0) dst[i] = v;
    }
}

// ---------------------------------------------------------------------------
// 3xTF32 GEMM: C(1024x1024) = A @ B, fp32-class accuracy on tensor cores.
// Tile M=128, N=64, BK=32. 128 threads / 4 warps; warp owns 32 rows (2 strips).
// hi/lo split: C ~= Ah*Bh + Ah*Bl + Al*Bh.
// ---------------------------------------------------------------------------
#define AP 36   // As pitch (floats)
#define BP 72   // Bs pitch (floats)
#define GEMM_SMEM ((128 * AP * 2 + 32 * BP * 2) * 4)

__global__ __launch_bounds__(128) void gemm3t_kernel(const float* __restrict__ A,
                                                     const float* __restrict__ Bm,
                                                     float* __restrict__ C) {
    extern __shared__ float sm[];
    float* Ah = sm;
    float* Al = Ah + 128 * AP;
    float* Bh = Al + 128 * AP;
    float* Bl = Bh + 32 * BP;

    const int t = threadIdx.x, w = t >> 5, lane = t & 31;
    const int g = lane >> 2, c = lane & 3;
    const int m0 = blockIdx.y * 128, n0 = blockIdx.x * 64;

    float o0[8][4] = {}, o1[8][4] = {};

    const int br = t >> 2, bc = (t & 3) * 4;

    for (int k0 = 0; k0 < 1024; k0 += 32) {
        // prefetch gmem
        float4 av[8], bv4[4];
        const float* ar = A + (size_t)(m0 + t) * 1024 + k0;
#pragma unroll
        for (int i = 0; i < 8; i++) av[i] = *(const float4*)(ar + i * 4);
        const float* brp = Bm + (size_t)(k0 + br) * 1024 + n0 + bc;
#pragma unroll
        for (int i = 0; i < 4; i++) bv4[i] = *(const float4*)(brp + i * 16);

        __syncthreads();
        // split + store
#pragma unroll
        for (int i = 0; i < 8; i++) {
            float xs[4] = {av[i].x, av[i].y, av[i].z, av[i].w};
#pragma unroll
            for (int j = 0; j < 4; j++) {
                float hi = __uint_as_float(f2tf32(xs[j]));
                float lo = xs[j] - hi;
                Ah[t * AP + i * 4 + j] = hi;
                Al[t * AP + i * 4 + j] = __uint_as_float(f2tf32(lo));
            }
        }
#pragma unroll
        for (int i = 0; i < 4; i++) {
            float xs[4] = {bv4[i].x, bv4[i].y, bv4[i].z, bv4[i].w};
#pragma unroll
            for (int j = 0; j < 4; j++) {
                float hi = __uint_as_float(f2tf32(xs[j]));
                float lo = xs[j] - hi;
                Bh[br * BP + bc + i * 16 + j] = hi;
                Bl[br * BP + bc + i * 16 + j] = __uint_as_float(f2tf32(lo));
            }
        }
        __syncthreads();

#pragma unroll
        for (int ks = 0; ks < 4; ks++) {
            unsigned int ah0[4], al0[4], ah1[4], al1[4];
            const int r0 = w * 32 + g, r1 = w * 32 + 16 + g;
            ah0[0] = __float_as_uint(Ah[r0 * AP + ks * 8 + c]);
            ah0[1] = __float_as_uint(Ah[(r0 + 8) * AP + ks * 8 + c]);
            ah0[2] = __float_as_uint(Ah[r0 * AP + ks * 8 + c + 4]);
            ah0[3] = __float_as_uint(Ah[(r0 + 8) * AP + ks * 8 + c + 4]);
            al0[0] = __float_as_uint(Al[r0 * AP + ks * 8 + c]);
            al0[1] = __float_as_uint(Al[(r0 + 8) * AP + ks * 8 + c]);
            al0[2] = __float_as_uint(Al[r0 * AP + ks * 8 + c + 4]);
            al0[3] = __float_as_uint(Al[(r0 + 8) * AP + ks * 8 + c + 4]);
            ah1[0] = __float_as_uint(Ah[r1 * AP + ks * 8 + c]);
            ah1[1] = __float_as_uint(Ah[(r1 + 8) * AP + ks * 8 + c]);
            ah1[2] = __float_as_uint(Ah[r1 * AP + ks * 8 + c + 4]);
            ah1[3] = __float_as_uint(Ah[(r1 + 8) * AP + ks * 8 + c + 4]);
            al1[0] = __float_as_uint(Al[r1 * AP + ks * 8 + c]);
            al1[1] = __float_as_uint(Al[(r1 + 8) * AP + ks * 8 + c]);
            al1[2] = __float_as_uint(Al[r1 * AP + ks * 8 + c + 4]);
            al1[3] = __float_as_uint(Al[(r1 + 8) * AP + ks * 8 + c + 4]);
#pragma unroll
            for (int nb = 0; nb < 8; nb++) {
                unsigned int bh[2], bl[2];
                bh[0] = __float_as_uint(Bh[(ks * 8 + c) * BP + nb * 8 + g]);
                bh[1] = __float_as_uint(Bh[(ks * 8 + c + 4) * BP + nb * 8 + g]);
                bl[0] = __float_as_uint(Bl[(ks * 8 + c) * BP + nb * 8 + g]);
                bl[1] = __float_as_uint(Bl[(ks * 8 + c + 4) * BP + nb * 8 + g]);
                mma_tf32(o0[nb], ah0, bh);
                mma_tf32(o0[nb], ah0, bl);
                mma_tf32(o0[nb], al0, bh);
                mma_tf32(o1[nb], ah1, bh);
                mma_tf32(o1[nb], ah1, bl);
                mma_tf32(o1[nb], al1, bh);
            }
        }
        __syncthreads();
    }

    // epilogue
#pragma unroll
    for (int sp = 0; sp < 2; sp++) {
        float(*oo)[4] = sp ? o1 : o0;
        int rowa = m0 + w * 32 + sp * 16 + g;
#pragma unroll
        for (int nb = 0; nb < 8; nb++) {
            float2 v0 = {oo[nb][0], oo[nb][1]};
            float2 v1 = {oo[nb][2], oo[nb][3]};
            *(float2*)(C + (size_t)rowa * 1024 + n0 + nb * 8 + 2 * c) = v0;
            *(float2*)(C + (size_t)(rowa + 8) * 1024 + n0 + nb * 8 + 2 * c) = v1;
        }
    }
}

// ---------------------------------------------------------------------------
// Flash attention, tf32 mma, 2 m-strips per warp for B-frag reuse.
// Block = (128-q rows, h, b), 128 threads / 4 warps, warp owns 32 rows.
// ---------------------------------------------------------------------------
#define KP 68
#define ATT_SMEM ((64 * KP + 4 * 32 * KP) * 4)

__device__ __forceinline__ void softmax_store(
    float (&s)[8][4], float (&o)[8][4],
    float& m0, float& m1, float& l0, float& l1,
    const unsigned int* mw, bool masked, float* prow, int g, int c)
{
    if (masked) {
#pragma unroll
        for (int nb = 0; nb < 8; nb++) {
            unsigned int wa = (nb < 4) ? mw[0] : mw[1];
            unsigned int wb = (nb < 4) ? mw[2] : mw[3];
            int bit0 = (nb & 3) * 8 + 2 * c;
            if (!((wa >> bit0) & 1u)) s[nb][0] = NEGF;
            if (!((wa >> (bit0 + 1)) & 1u)) s[nb][1] = NEGF;
            if (!((wb >> bit0) & 1u)) s[nb][2] = NEGF;
            if (!((wb >> (bit0 + 1)) & 1u)) s[nb][3] = NEGF;
        }
    }
    float mx0 = NEGF, mx1 = NEGF;
#pragma unroll
    for (int nb = 0; nb < 8; nb++) {
        mx0 = fmaxf(mx0, fmaxf(s[nb][0], s[nb][1]));
        mx1 = fmaxf(mx1, fmaxf(s[nb][2], s[nb][3]));
    }
    mx0 = fmaxf(mx0, __shfl_xor_sync(0xffffffffu, mx0, 1));
    mx0 = fmaxf(mx0, __shfl_xor_sync(0xffffffffu, mx0, 2));
    mx1 = fmaxf(mx1, __shfl_xor_sync(0xffffffffu, mx1, 1));
    mx1 = fmaxf(mx1, __shfl_xor_sync(0xffffffffu, mx1, 2));
    float mn0 = fmaxf(m0, mx0), mn1 = fmaxf(m1, mx1);
    float a0 = __expf(m0 - mn0), a1 = __expf(m1 - mn1);
    m0 = mn0;
    m1 = mn1;
    float ps0 = 0.f, ps1 = 0.f;
#pragma unroll
    for (int nb = 0; nb < 8; nb++) {
        s[nb][0] = __expf(s[nb][0] - mn0);
        s[nb][1] = __expf(s[nb][1] - mn0);
        s[nb][2] = __expf(s[nb][2] - mn1);
        s[nb][3] = __expf(s[nb][3] - mn1);
        ps0 += s[nb][0] + s[nb][1];
        ps1 += s[nb][2] + s[nb][3];
    }
    ps0 += __shfl_xor_sync(0xffffffffu, ps0, 1);
    ps0 += __shfl_xor_sync(0xffffffffu, ps0, 2);
    ps1 += __shfl_xor_sync(0xffffffffu, ps1, 1);
    ps1 += __shfl_xor_sync(0xffffffffu, ps1, 2);
    l0 = l0 * a0 + ps0;
    l1 = l1 * a1 + ps1;
#pragma unroll
    for (int nb = 0; nb < 8; nb++) {
        o[nb][0] *= a0;
        o[nb][1] *= a0;
        o[nb][2] *= a1;
        o[nb][3] *= a1;
    }
    // store P (tf32 bits)
#pragma unroll
    for (int nb = 0; nb < 8; nb++) {
        float2 v0, v1;
        v0.x = __uint_as_float(f2tf32(s[nb][0]));
        v0.y = __uint_as_float(f2tf32(s[nb][1]));
        v1.x = __uint_as_float(f2tf32(s[nb][2]));
        v1.y = __uint_as_float(f2tf32(s[nb][3]));
        *(float2*)&prow[g * KP + nb * 8 + 2 * c] = v0;
        *(float2*)&prow[(g + 8) * KP + nb * 8 + 2 * c] = v1;
    }
}

__global__ __launch_bounds__(128) void attn_mma2_kernel(const float* __restrict__ gc) {
    extern __shared__ float smem[];
    float* Ks = smem;                        // [64][KP]
    const int b = blockIdx.z, h = blockIdx.y, q0 = blockIdx.x * 128;
    const int t = threadIdx.x;
    const int w = t >> 5, lane = t & 31;
    const int g = lane >> 2, c = lane & 3;
    const int rbase = q0 + w * 32;
    float* pw = smem + 64 * KP + w * 32 * KP;  // per-warp P [32][KP]

    // Q A-fragments for both strips, scale folded
    unsigned int qa[2][8][4];
#pragma unroll
    for (int sp = 0; sp < 2; sp++) {
        const float* qb = g_q + (size_t)(b * NXQ + rbase + sp * 16 + g) * DD + h * HDD;
#pragma unroll
        for (int ks = 0; ks < 8; ks++) {
            qa[sp][ks][0] = f2tf32(qb[ks * 8 + c] * 0.125f);
            qa[sp][ks][1] = f2tf32(qb[8 * DD + ks * 8 + c] * 0.125f);
            qa[sp][ks][2] = f2tf32(qb[ks * 8 + c + 4] * 0.125f);
            qa[sp][ks][3] = f2tf32(qb[8 * DD + ks * 8 + c + 4] * 0.125f);
        }
    }

    float o0[8][4] = {}, o1[8][4] = {};
    float m0a = NEGF, m0b = NEGF, m1a = NEGF, m1b = NEGF;
    float l0a = 0.f, l0b = 0.f, l1a = 0.f, l1b = 0.f;

    // K loader: conflict-free store mapping (row = t&63, col = (t>>6)*32)
    const int lrow = t & 63, lc0 = (t >> 6) * 32;

    for (int kt = 0; kt < 72; kt++) {
        const bool isq = (kt < 8);

        float4 kv[8];
        {
            const float* src = isq
                ? g_q + (size_t)(b * NXQ + kt * 64 + lrow) * DD + h * HDD + lc0
                : gc  + (size_t)(b * NCC + (kt - 8) * 64 + lrow) * DD + h * HDD + lc0;
#pragma unroll
            for (int i = 0; i < 8; i++) kv[i] = *(const float4*)(src + i * 4);
        }
        unsigned int mw[2][4] = {{~0u, ~0u, ~0u, ~0u}, {~0u, ~0u, ~0u, ~0u}};
        if (!isq) {
#pragma unroll
            for (int sp = 0; sp < 2; sp++) {
                const unsigned int* mr = g_mbits +
                    (size_t)(b * NXQ + rbase + sp * 16 + g) * (NCC / 32) + (kt - 8) * 2;
                mw[sp][0] = mr[0];
                mw[sp][1] = mr[1];
                mw[sp][2] = mr[8 * (NCC / 32)];
                mw[sp][3] = mr[8 * (NCC / 32) + 1];
            }
        }

        __syncthreads();
#pragma unroll
        for (int i = 0; i < 8; i++) {
            float4 cv;
            cv.x = __uint_as_float(f2tf32(kv[i].x));
            cv.y = __uint_as_float(f2tf32(kv[i].y));
            cv.z = __uint_as_float(f2tf32(kv[i].z));
            cv.w = __uint_as_float(f2tf32(kv[i].w));
            *(float4*)&Ks[lrow * KP + lc0 + i * 4] = cv;
        }
        __syncthreads();

        // S = (Q*scale) @ K^T  — B-frags shared by both strips
        float s0[8][4] = {}, s1[8][4] = {};
#pragma unroll
        for (int ks = 0; ks < 8; ks++) {
#pragma unroll
            for (int nb = 0; nb < 8; nb++) {
                unsigned int bk[2];
                bk[0] = __float_as_uint(Ks[(nb * 8 + g) * KP + ks * 8 + c]);
                bk[1] = __float_as_uint(Ks[(nb * 8 + g) * KP + ks * 8 + c + 4]);
                mma_tf32(s0[nb], qa[0][ks], bk);
                mma_tf32(s1[nb], qa[1][ks], bk);
            }
        }

        softmax_store(s0, o0, m0a, m0b, l0a, l0b, mw[0], !isq, pw, g, c);
        softmax_store(s1, o1, m1a, m1b, l1a, l1b, mw[1], !isq, pw + 16 * KP, g, c);
        __syncwarp();

        // O += P @ V (V == K tile) — B-frags shared by both strips
#pragma unroll
        for (int ks = 0; ks < 8; ks++) {
            unsigned int pa0[4], pa1[4];
            pa0[0] = __float_as_uint(pw[g * KP + ks * 8 + c]);
            pa0[1] = __float_as_uint(pw[(g + 8) * KP + ks * 8 + c]);
            pa0[2] = __float_as_uint(pw[g * KP + ks * 8 + c + 4]);
            pa0[3] = __float_as_uint(pw[(g + 8) * KP + ks * 8 + c + 4]);
            pa1[0] = __float_as_uint(pw[(16 + g) * KP + ks * 8 + c]);
            pa1[1] = __float_as_uint(pw[(24 + g) * KP + ks * 8 + c]);
            pa1[2] = __float_as_uint(pw[(16 + g) * KP + ks * 8 + c + 4]);
            pa1[3] = __float_as_uint(pw[(24 + g) * KP + ks * 8 + c + 4]);
#pragma unroll
            for (int nb = 0; nb < 8; nb++) {
                unsigned int bv[2];
                bv[0] = __float_as_uint(Ks[(ks * 8 + c) * KP + nb * 8 + g]);
                bv[1] = __float_as_uint(Ks[(ks * 8 + c + 4) * KP + nb * 8 + g]);
                mma_tf32(o0[nb], pa0, bv);
                mma_tf32(o1[nb], pa1, bv);
            }
        }
        __syncwarp();
    }

    // epilogue
#pragma unroll
    for (int sp = 0; sp < 2; sp++) {
        float(*oo)[4] = sp ? o1 : o0;
        float la = sp ? l1a : l0a, lb = sp ? l1b : l0b;
        float inva = 1.0f / la, invb = 1.0f / lb;
        float* ob = g_attn + (size_t)(b * NXQ + rbase + sp * 16 + g) * DD + h * HDD;
#pragma unroll
        for (int nb = 0; nb < 8; nb++) {
            float2 v0 = {oo[nb][0] * inva, oo[nb][1] * inva};
            float2 v1 = {oo[nb][2] * invb, oo[nb][3] * invb};
            *(float2*)(ob + nb * 8 + 2 * c) = v0;
            *(float2*)(ob + 8 * DD + nb * 8 + 2 * c) = v1;
        }
    }
}

// ---------------------------------------------------------------------------
// kv0: out2[((b*16+h)*4096 + k)*64 + d] = c[(b*4096+k)*1024 + h*64 + d]
// ---------------------------------------------------------------------------
__global__ __launch_bounds__(256) void kv0_kernel(const float* __restrict__ c,
                                                  float* __restrict__ out2) {
    int idx = blockIdx.x * 256 + threadIdx.x;
    if (idx >= 2097152) return;
    int d4 = idx & 15;
    int k = (idx >> 4) & 4095;
    int h = (idx >> 16) & 15;
    int b = idx >> 20;
    float4 v = *(const float4*)(c + (size_t)(b * NCC + k) * DD + h * HDD + d4 * 4);
    *(float4*)(out2 + (size_t)idx * 4) = v;
}

// ---------------------------------------------------------------------------
extern "C" void kernel_launch(void* const* d_in, const int* in_sizes, int n_in,
                              void* d_out, int out_size) {
    const float* x = (const float*)d_in[0];
    const float* c = (const float*)d_in[1];
    const int* mask = (const int*)d_in[2];
    const float* lnw = (const float*)d_in[3];
    const float* lnb = (const float*)d_in[4];
    const float* Wq = (const float*)d_in[5];
    const float* Wo = (const float*)d_in[6];
    float* out = (float*)d_out;

    float *p_xn, *p_q, *p_attn;
    cudaGetSymbolAddress((void**)&p_xn, g_xn);
    cudaGetSymbolAddress((void**)&p_q, g_q);
    cudaGetSymbolAddress((void**)&p_attn, g_attn);

    cudaFuncSetAttribute(attn_mma2_kernel, cudaFuncAttributeMaxDynamicSharedMemorySize,
                         ATT_SMEM);
    cudaFuncSetAttribute(gemm3t_kernel, cudaFuncAttributeMaxDynamicSharedMemorySize,
                         GEMM_SMEM);

    // 0) pack mask
    maskpack_kernel<<<MROWS / 8, 256>>>(mask);

    // 1) LayerNorm
    ln_kernel<<<MROWS, 256>>>(x, lnw, lnb);

    // 2) Q = xn @ Wq  (3xTF32 tensor cores)
    gemm3t_kernel<<<dim3(16, 8), 128, GEMM_SMEM>>>(p_xn, Wq, p_q);

    // 3) Flash attention (tf32 tensor cores, 2 strips/warp)
    attn_mma2_kernel<<<dim3(NXQ / 128, HH, BB), 128, ATT_SMEM>>>(c);

    // 4) o = a @ Wo  (3xTF32, straight into output)
    gemm3t_kernel<<<dim3(16, 8), 128, GEMM_SMEM>>>(p_attn, Wo, out);

    // 5) kv0 transpose
    if (out_size >= 9437184) {
        kv0_kernel<<<2097152 / 256, 256>>>(c, out + 1048576);
    }
}